// round 13
// baseline (speedup 1.0000x reference)
#include <cuda_runtime.h>
#include <math.h>

// Problem constants (fixed-shape problem)
#define NTOK  8192
#define DDIM  1024
#define EEXP  64
#define RRANK 64
#define GGRP  8
#define MLOC  8

#define TILE_T 32           // tokens per expert tile
#define MAX_TILES 512       // per slot: <= N/TILE_T + E = 320

// ---------------- scratch (device globals; no allocations) ----------------
__device__ int   g_eid[NTOK * 2];      // global expert id per (token, slot)
__device__ float g_gate2[NTOK * 2];    // gate per (token, slot)
__device__ int   g_cnt[2][EEXP];
__device__ int   g_off[2][EEXP];
__device__ int   g_fill[2][EEXP];
__device__ int   g_tok[2][NTOK];       // token index, grouped by expert, per slot
__device__ float g_tg[2][NTOK];        // matching gate
__device__ int   g_tiles[2][MAX_TILES];// packed: (e<<16) | tile_index_within_expert
__device__ int   g_ntiles[2];
__device__ float g_extra[NTOK * DDIM]; // slot-1 partial output (merged by add_kernel)

// ---------------- init: zero counters ----------------
__global__ void init_kernel() {
    int t = threadIdx.x;
    if (t < EEXP) {
        g_cnt[0][t] = 0; g_cnt[1][t] = 0;
        g_fill[0][t] = 0; g_fill[1][t] = 0;
    }
    if (t == 0) { g_ntiles[0] = 0; g_ntiles[1] = 0; }
}

// ---------------- routing: one warp per token (unchanged, verified) ----------------
__global__ void routing_kernel(const float* __restrict__ h,
                               const float* __restrict__ Wg,
                               const float* __restrict__ bg,
                               const float* __restrict__ Wloc,
                               float* __restrict__ o_eid,    // may be null
                               float* __restrict__ o_gate,   // may be null
                               float* __restrict__ o_grp,    // may be null
                               int n)
{
    int warp = (blockIdx.x * blockDim.x + threadIdx.x) >> 5;
    int lane = threadIdx.x & 31;
    if (warp >= n) return;

    const float* hrow = h + (size_t)warp * DDIM;

    float hv[32];
#pragma unroll
    for (int i = 0; i < 32; i++) hv[i] = hrow[i * 32 + lane];

    // ---- stage 1: group scores (G=8) ----
    float sg[GGRP];
#pragma unroll
    for (int g = 0; g < GGRP; g++) sg[g] = 0.f;
#pragma unroll
    for (int i = 0; i < 32; i++) {
        int d = i * 32 + lane;
        const float4* wp = (const float4*)(Wg + (size_t)d * GGRP);
        float4 wa = wp[0], wb = wp[1];
        float x = hv[i];
        sg[0] += x * wa.x; sg[1] += x * wa.y; sg[2] += x * wa.z; sg[3] += x * wa.w;
        sg[4] += x * wb.x; sg[5] += x * wb.y; sg[6] += x * wb.z; sg[7] += x * wb.w;
    }
#pragma unroll
    for (int g = 0; g < GGRP; g++) {
#pragma unroll
        for (int off = 16; off > 0; off >>= 1)
            sg[g] += __shfl_xor_sync(0xFFFFFFFFu, sg[g], off);
        sg[g] += bg[g];
    }
    int gi = 0; float best = sg[0];
#pragma unroll
    for (int g = 1; g < GGRP; g++) if (sg[g] > best) { best = sg[g]; gi = g; }

    // ---- stage 2: local scores for selected group (M=8) ----
    float sl[MLOC];
#pragma unroll
    for (int m = 0; m < MLOC; m++) sl[m] = 0.f;
    const float* wl = Wloc + (size_t)gi * DDIM * MLOC;
#pragma unroll
    for (int i = 0; i < 32; i++) {
        int d = i * 32 + lane;
        const float4* wp = (const float4*)(wl + (size_t)d * MLOC);
        float4 wa = wp[0], wb = wp[1];
        float x = hv[i];
        sl[0] += x * wa.x; sl[1] += x * wa.y; sl[2] += x * wa.z; sl[3] += x * wa.w;
        sl[4] += x * wb.x; sl[5] += x * wb.y; sl[6] += x * wb.z; sl[7] += x * wb.w;
    }
#pragma unroll
    for (int m = 0; m < MLOC; m++) {
#pragma unroll
        for (int off = 16; off > 0; off >>= 1)
            sl[m] += __shfl_xor_sync(0xFFFFFFFFu, sl[m], off);
    }
    int m1 = 0; float v1 = sl[0];
#pragma unroll
    for (int m = 1; m < MLOC; m++) if (sl[m] > v1) { v1 = sl[m]; m1 = m; }
    int m2 = -1; float v2 = -INFINITY;
#pragma unroll
    for (int m = 0; m < MLOC; m++) if (m != m1 && sl[m] > v2) { v2 = sl[m]; m2 = m; }

    float e2 = expf(v2 - v1);
    float inv = 1.0f / (1.0f + e2);
    float gate0 = inv;
    float gate1 = e2 * inv;

    int eid0 = gi * MLOC + m1;
    int eid1 = gi * MLOC + m2;

    if (lane == 0) {
        g_eid[2 * warp + 0] = eid0;
        g_eid[2 * warp + 1] = eid1;
        g_gate2[2 * warp + 0] = gate0;
        g_gate2[2 * warp + 1] = gate1;
        atomicAdd(&g_cnt[0][eid0], 1);
        atomicAdd(&g_cnt[1][eid1], 1);
        if (o_eid)  { o_eid[2 * warp + 0] = (float)eid0; o_eid[2 * warp + 1] = (float)eid1; }
        if (o_gate) { o_gate[2 * warp + 0] = gate0;      o_gate[2 * warp + 1] = gate1; }
        if (o_grp)  { o_grp[warp] = (float)gi; }
    }
}

// ---------------- prefix sums + tile lists (tiny; single thread) ----------------
__global__ void prefix_kernel() {
    if (threadIdx.x != 0 || blockIdx.x != 0) return;
#pragma unroll
    for (int s = 0; s < 2; s++) {
        int acc = 0, nt = 0;
        for (int e = 0; e < EEXP; e++) {
            g_off[s][e] = acc;
            int c = g_cnt[s][e];
            acc += c;
            int t = (c + TILE_T - 1) / TILE_T;
            for (int i = 0; i < t && nt < MAX_TILES; i++)
                g_tiles[s][nt++] = (e << 16) | i;
        }
        g_ntiles[s] = nt;
    }
}

// ---------------- scatter tokens into per-expert, per-slot buckets ----------------
__global__ void scatter_kernel(int n) {
    int t = blockIdx.x * blockDim.x + threadIdx.x;
    if (t >= n) return;
#pragma unroll
    for (int j = 0; j < 2; j++) {
        int e = g_eid[2 * t + j];
        int p = g_off[j][e] + atomicAdd(&g_fill[j][e], 1);
        g_tok[j][p] = t;
        g_tg[j][p]  = g_gate2[2 * t + j];
    }
}

// ---------------- expert compute: one tile = (slot, expert, 32 tokens) ----------------
// Both slots in ONE launch (slot0 -> out, slot1 -> g_extra); no atomics.
// Phase 1: A = gate * relu(H @ W1[e])  (32 x 64), ping-pong k-chunks of 32, reg-prefetch.
// Phase 2: O = A @ W2[e]               (32 x 1024), 64-col tiles, W2 ping-pong,
//          ONE barrier per tile-iteration (STS overlapped with compute).
// Thread map: tt = tid&15 -> tokens {2tt, 2tt+1}; rg = tid>>4 -> 4 cols {4rg..4rg+3}.
__global__ void __launch_bounds__(256)
expert_kernel(const float* __restrict__ h,
              const float* __restrict__ W1,
              const float* __restrict__ W2,
              float* __restrict__ out)
{
    // s_u aliases: phase1 H^T ping-pong [2][32][34] (2176 floats)
    //              phase2 A^T           [64][34]    (2176 floats)
    __shared__ __align__(16) float s_u[2176];
    // s_w: phase1 W1 ping-pong at offsets {0, 2048} (each 32x64);
    //      phase2 W2 ping-pong at offsets {0, 4096} (each 64x64).
    __shared__ __align__(16) float s_w[8192];
    __shared__ int   tok_s[TILE_T];
    __shared__ float gsc[TILE_T];

#define HT(b, k, t) s_u[(b) * 1088 + (k) * 34 + (t)]
#define AT(r, t)    s_u[(r) * 34 + (t)]

    int tid = threadIdx.x;
    int tt = tid & 15, rg = tid >> 4;
    int t0 = 2 * tt, t1 = t0 + 1;
    int r0 = rg * 4;

    // fill index precompute
    int fh_t = (tid >> 5);           // + 8*i  -> token for H fill
    int fh_k = tid & 31;             // k within chunk
    int fw_r = tid >> 6;             // + 4*i  -> row for W fills (64-wide)
    int fw_c = tid & 63;

    int nt0 = g_ntiles[0];
    int ntt = nt0 + g_ntiles[1];

    for (int tile = blockIdx.x; tile < ntt; tile += gridDim.x) {
        int slot = (tile >= nt0) ? 1 : 0;
        int tloc = slot ? tile - nt0 : tile;
        int desc = g_tiles[slot][tloc];
        int e  = desc >> 16;
        int ti = desc & 0xFFFF;
        int cnt_e = g_cnt[slot][e];
        int base  = g_off[slot][e] + ti * TILE_T;
        int nv = cnt_e - ti * TILE_T;
        if (nv > TILE_T) nv = TILE_T;

        if (tid < TILE_T) {
            int rr = tid < nv ? tid : (nv - 1);   // clamp; invalid rows masked at store
            tok_s[tid] = g_tok[slot][base + rr];
            gsc[tid]   = g_tg[slot][base + rr];
        }
        __syncthreads();

        const float* W1e = W1 + (size_t)e * DDIM * RRANK;

        // token row pointers for this thread's H-fill lanes (tokens fh_t, fh_t+8, +16, +24)
        const float* hp0 = h + (size_t)tok_s[fh_t +  0] * DDIM + fh_k;
        const float* hp1 = h + (size_t)tok_s[fh_t +  8] * DDIM + fh_k;
        const float* hp2 = h + (size_t)tok_s[fh_t + 16] * DDIM + fh_k;
        const float* hp3 = h + (size_t)tok_s[fh_t + 24] * DDIM + fh_k;

        float hr[4], wr[8];
        // preload k-tile 0
        hr[0] = hp0[0]; hr[1] = hp1[0]; hr[2] = hp2[0]; hr[3] = hp3[0];
#pragma unroll
        for (int i = 0; i < 8; i++)
            wr[i] = W1e[(size_t)(fw_r + 4 * i) * RRANK + fw_c];
        // store buf 0
        HT(0, fh_k, fh_t +  0) = hr[0];
        HT(0, fh_k, fh_t +  8) = hr[1];
        HT(0, fh_k, fh_t + 16) = hr[2];
        HT(0, fh_k, fh_t + 24) = hr[3];
#pragma unroll
        for (int i = 0; i < 8; i++)
            s_w[(fw_r + 4 * i) * 64 + fw_c] = wr[i];
        __syncthreads();

        // ---------------- phase 1 ----------------
        float a0[4] = {0.f, 0.f, 0.f, 0.f};
        float a1[4] = {0.f, 0.f, 0.f, 0.f};

        for (int kt = 0; kt < DDIM / 32; kt++) {
            int b = kt & 1;
            if (kt < DDIM / 32 - 1) {
                int k0 = (kt + 1) * 32;
                hr[0] = hp0[k0]; hr[1] = hp1[k0]; hr[2] = hp2[k0]; hr[3] = hp3[k0];
#pragma unroll
                for (int i = 0; i < 8; i++)
                    wr[i] = W1e[(size_t)(k0 + fw_r + 4 * i) * RRANK + fw_c];
            }
            const float* wb = s_w + b * 2048;
#pragma unroll
            for (int kk = 0; kk < 32; kk++) {
                float2 hp = *(const float2*)&HT(b, kk, t0);
                float4 w  = *(const float4*)&wb[kk * 64 + r0];
                a0[0] += hp.x * w.x; a0[1] += hp.x * w.y; a0[2] += hp.x * w.z; a0[3] += hp.x * w.w;
                a1[0] += hp.y * w.x; a1[1] += hp.y * w.y; a1[2] += hp.y * w.z; a1[3] += hp.y * w.w;
            }
            if (kt < DDIM / 32 - 1) {
                int nb = 1 - b;
                HT(nb, fh_k, fh_t +  0) = hr[0];
                HT(nb, fh_k, fh_t +  8) = hr[1];
                HT(nb, fh_k, fh_t + 16) = hr[2];
                HT(nb, fh_k, fh_t + 24) = hr[3];
#pragma unroll
                for (int i = 0; i < 8; i++)
                    s_w[nb * 2048 + (fw_r + 4 * i) * 64 + fw_c] = wr[i];
            }
            __syncthreads();
        }

        // ---------------- A^T write (aliases H^T region) + W2 tile-0 prefetch ----------------
        const float* W2e = W2 + (size_t)e * RRANK * DDIM;
        float wr2[16];
#pragma unroll
        for (int i = 0; i < 16; i++)
            wr2[i] = W2e[(size_t)(fw_r + 4 * i) * DDIM + fw_c];

        float gt0 = gsc[t0], gt1 = gsc[t1];
#pragma unroll
        for (int j = 0; j < 4; j++)
            *(float2*)&AT(r0 + j, t0) =
                make_float2(fmaxf(a0[j], 0.f) * gt0, fmaxf(a1[j], 0.f) * gt1);

#pragma unroll
        for (int i = 0; i < 16; i++)
            s_w[(fw_r + 4 * i) * 64 + fw_c] = wr2[i];
        __syncthreads();   // A^T + W2 buf0 visible

        // ---------------- phase 2 (W2 ping-pong; one barrier per ct) ----------------
        bool v0 = (t0 < nv), v1 = (t1 < nv);
        size_t ob0 = (size_t)tok_s[t0] * DDIM;
        size_t ob1 = (size_t)tok_s[t1] * DDIM;
        float* dst = slot ? g_extra : out;

        for (int ct = 0; ct < 16; ct++) {
            if (ct < 15) {
                int c0 = (ct + 1) * 64;
#pragma unroll
                for (int i = 0; i < 16; i++)
                    wr2[i] = W2e[(size_t)(fw_r + 4 * i) * DDIM + c0 + fw_c];
            }
            const float* wb = s_w + (ct & 1) * 4096;
            float o0[4] = {0.f, 0.f, 0.f, 0.f};
            float o1[4] = {0.f, 0.f, 0.f, 0.f};
#pragma unroll
            for (int r = 0; r < RRANK; r++) {
                float2 ap = *(const float2*)&AT(r, t0);
                float4 w  = *(const float4*)&wb[r * 64 + r0];
                o0[0] += ap.x * w.x; o0[1] += ap.x * w.y; o0[2] += ap.x * w.z; o0[3] += ap.x * w.w;
                o1[0] += ap.y * w.x; o1[1] += ap.y * w.y; o1[2] += ap.y * w.z; o1[3] += ap.y * w.w;
            }
            if (ct < 15) {
                int nb = ((ct + 1) & 1) * 4096;
#pragma unroll
                for (int i = 0; i < 16; i++)
                    s_w[nb + (fw_r + 4 * i) * 64 + fw_c] = wr2[i];
            }
            int c = ct * 64 + r0;
            if (v0) *(float4*)&dst[ob0 + c] = make_float4(o0[0], o0[1], o0[2], o0[3]);
            if (v1) *(float4*)&dst[ob1 + c] = make_float4(o1[0], o1[1], o1[2], o1[3]);
            __syncthreads();   // next buf ready; current buf reads done before its rewrite at ct+2
        }
        // final barrier above also protects s_u/tok_s/gsc reuse next tile
    }
#undef HT
#undef AT
}

// ---------------- merge: out += g_extra ----------------
__global__ void add_kernel(float* __restrict__ out, int n4) {
    int i = blockIdx.x * blockDim.x + threadIdx.x;
    int stride = gridDim.x * blockDim.x;
    const float4* ex = (const float4*)g_extra;
    float4* o = (float4*)out;
    for (; i < n4; i += stride) {
        float4 a = o[i], b = ex[i];
        a.x += b.x; a.y += b.y; a.z += b.z; a.w += b.w;
        o[i] = a;
    }
}

// ---------------- launch ----------------
extern "C" void kernel_launch(void* const* d_in, const int* in_sizes, int n_in,
                              void* d_out, int out_size)
{
    const float* h    = (const float*)d_in[0];
    const float* Wg   = (const float*)d_in[1];
    const float* bg   = (const float*)d_in[2];
    const float* Wloc = (const float*)d_in[3];
    const float* W1   = (const float*)d_in[4];
    const float* W2   = (const float*)d_in[5];

    int n = in_sizes[0] / DDIM;                 // 8192
    if (n > NTOK) n = NTOK;

    float* out = (float*)d_out;

    // Optional concatenated tail outputs: out(N*D), expert_ids(2N), gate(2N), group_idx(N)
    size_t need = (size_t)n * DDIM + 5 * (size_t)n;
    float* o_eid  = nullptr;
    float* o_gate = nullptr;
    float* o_grp  = nullptr;
    if ((size_t)out_size >= need) {
        o_eid  = out + (size_t)n * DDIM;
        o_gate = o_eid + 2 * (size_t)n;
        o_grp  = o_gate + 2 * (size_t)n;
    }

    init_kernel<<<1, 128>>>();
    routing_kernel<<<(n + 7) / 8, 256>>>(h, Wg, bg, Wloc, o_eid, o_gate, o_grp, n);
    prefix_kernel<<<1, 32>>>();
    scatter_kernel<<<(n + 255) / 256, 256>>>(n);
    // Both slots in one wave: slot0 tiles write `out`, slot1 tiles write g_extra
    expert_kernel<<<592, 256>>>(h, W1, W2, out);
    // out += g_extra
    add_kernel<<<1024, 256>>>(out, n * DDIM / 4);
}

// round 14
// speedup vs baseline: 1.6435x; 1.6435x over previous
#include <cuda_runtime.h>
#include <math.h>

// Problem constants (fixed-shape problem)
#define NTOK  8192
#define DDIM  1024
#define EEXP  64
#define RRANK 64
#define GGRP  8
#define MLOC  8

#define TILE_T 32           // tokens per expert tile
#define MAX_TILES 512       // per slot: <= N/TILE_T + E = 320

// ---------------- scratch (device globals; no allocations) ----------------
__device__ int   g_eid[NTOK * 2];      // global expert id per (token, slot)
__device__ float g_gate2[NTOK * 2];    // gate per (token, slot)
__device__ int   g_cnt[2][EEXP];
__device__ int   g_off[2][EEXP];
__device__ int   g_fill[2][EEXP];
__device__ int   g_tok[2][NTOK];       // token index, grouped by expert, per slot
__device__ float g_tg[2][NTOK];        // matching gate
__device__ int   g_tiles[2][MAX_TILES];// packed: (e<<16) | tile_index_within_expert
__device__ int   g_ntiles[2];
__device__ float g_extra[NTOK * DDIM]; // slot-1 partial output (merged by add_kernel)

// ---------------- init: zero counters ----------------
__global__ void init_kernel() {
    int t = threadIdx.x;
    if (t < EEXP) {
        g_cnt[0][t] = 0; g_cnt[1][t] = 0;
        g_fill[0][t] = 0; g_fill[1][t] = 0;
    }
    if (t == 0) { g_ntiles[0] = 0; g_ntiles[1] = 0; }
}

// ---------------- routing: one warp per token (unchanged, verified) ----------------
__global__ void routing_kernel(const float* __restrict__ h,
                               const float* __restrict__ Wg,
                               const float* __restrict__ bg,
                               const float* __restrict__ Wloc,
                               float* __restrict__ o_eid,    // may be null
                               float* __restrict__ o_gate,   // may be null
                               float* __restrict__ o_grp,    // may be null
                               int n)
{
    int warp = (blockIdx.x * blockDim.x + threadIdx.x) >> 5;
    int lane = threadIdx.x & 31;
    if (warp >= n) return;

    const float* hrow = h + (size_t)warp * DDIM;

    float hv[32];
#pragma unroll
    for (int i = 0; i < 32; i++) hv[i] = hrow[i * 32 + lane];

    // ---- stage 1: group scores (G=8) ----
    float sg[GGRP];
#pragma unroll
    for (int g = 0; g < GGRP; g++) sg[g] = 0.f;
#pragma unroll
    for (int i = 0; i < 32; i++) {
        int d = i * 32 + lane;
        const float4* wp = (const float4*)(Wg + (size_t)d * GGRP);
        float4 wa = wp[0], wb = wp[1];
        float x = hv[i];
        sg[0] += x * wa.x; sg[1] += x * wa.y; sg[2] += x * wa.z; sg[3] += x * wa.w;
        sg[4] += x * wb.x; sg[5] += x * wb.y; sg[6] += x * wb.z; sg[7] += x * wb.w;
    }
#pragma unroll
    for (int g = 0; g < GGRP; g++) {
#pragma unroll
        for (int off = 16; off > 0; off >>= 1)
            sg[g] += __shfl_xor_sync(0xFFFFFFFFu, sg[g], off);
        sg[g] += bg[g];
    }
    int gi = 0; float best = sg[0];
#pragma unroll
    for (int g = 1; g < GGRP; g++) if (sg[g] > best) { best = sg[g]; gi = g; }

    // ---- stage 2: local scores for selected group (M=8) ----
    float sl[MLOC];
#pragma unroll
    for (int m = 0; m < MLOC; m++) sl[m] = 0.f;
    const float* wl = Wloc + (size_t)gi * DDIM * MLOC;
#pragma unroll
    for (int i = 0; i < 32; i++) {
        int d = i * 32 + lane;
        const float4* wp = (const float4*)(wl + (size_t)d * MLOC);
        float4 wa = wp[0], wb = wp[1];
        float x = hv[i];
        sl[0] += x * wa.x; sl[1] += x * wa.y; sl[2] += x * wa.z; sl[3] += x * wa.w;
        sl[4] += x * wb.x; sl[5] += x * wb.y; sl[6] += x * wb.z; sl[7] += x * wb.w;
    }
#pragma unroll
    for (int m = 0; m < MLOC; m++) {
#pragma unroll
        for (int off = 16; off > 0; off >>= 1)
            sl[m] += __shfl_xor_sync(0xFFFFFFFFu, sl[m], off);
    }
    int m1 = 0; float v1 = sl[0];
#pragma unroll
    for (int m = 1; m < MLOC; m++) if (sl[m] > v1) { v1 = sl[m]; m1 = m; }
    int m2 = -1; float v2 = -INFINITY;
#pragma unroll
    for (int m = 0; m < MLOC; m++) if (m != m1 && sl[m] > v2) { v2 = sl[m]; m2 = m; }

    float e2 = expf(v2 - v1);
    float inv = 1.0f / (1.0f + e2);
    float gate0 = inv;
    float gate1 = e2 * inv;

    int eid0 = gi * MLOC + m1;
    int eid1 = gi * MLOC + m2;

    if (lane == 0) {
        g_eid[2 * warp + 0] = eid0;
        g_eid[2 * warp + 1] = eid1;
        g_gate2[2 * warp + 0] = gate0;
        g_gate2[2 * warp + 1] = gate1;
        atomicAdd(&g_cnt[0][eid0], 1);
        atomicAdd(&g_cnt[1][eid1], 1);
        if (o_eid)  { o_eid[2 * warp + 0] = (float)eid0; o_eid[2 * warp + 1] = (float)eid1; }
        if (o_gate) { o_gate[2 * warp + 0] = gate0;      o_gate[2 * warp + 1] = gate1; }
        if (o_grp)  { o_grp[warp] = (float)gi; }
    }
}

// ---------------- prefix sums + tile lists (tiny; single thread) ----------------
__global__ void prefix_kernel() {
    if (threadIdx.x != 0 || blockIdx.x != 0) return;
#pragma unroll
    for (int s = 0; s < 2; s++) {
        int acc = 0, nt = 0;
        for (int e = 0; e < EEXP; e++) {
            g_off[s][e] = acc;
            int c = g_cnt[s][e];
            acc += c;
            int t = (c + TILE_T - 1) / TILE_T;
            for (int i = 0; i < t && nt < MAX_TILES; i++)
                g_tiles[s][nt++] = (e << 16) | i;
        }
        g_ntiles[s] = nt;
    }
}

// ---------------- scatter tokens into per-expert, per-slot buckets ----------------
__global__ void scatter_kernel(int n) {
    int t = blockIdx.x * blockDim.x + threadIdx.x;
    if (t >= n) return;
#pragma unroll
    for (int j = 0; j < 2; j++) {
        int e = g_eid[2 * t + j];
        int p = g_off[j][e] + atomicAdd(&g_fill[j][e], 1);
        g_tok[j][p] = t;
        g_tg[j][p]  = g_gate2[2 * t + j];
    }
}

// ---------------- tf32 helpers ----------------
__device__ __forceinline__ float to_tf32(float x) {
    float y;
    asm("cvt.rna.tf32.f32 %0, %1;" : "=f"(y) : "f"(x));
    return y;
}

#define MMA_TF32(d, a0, a1, a2, a3, b0, b1)                                   \
    asm volatile(                                                             \
        "mma.sync.aligned.m16n8k8.row.col.f32.tf32.tf32.f32 "                 \
        "{%0,%1,%2,%3}, {%4,%5,%6,%7}, {%8,%9}, {%0,%1,%2,%3};"               \
        : "+f"((d)[0]), "+f"((d)[1]), "+f"((d)[2]), "+f"((d)[3])              \
        : "r"(__float_as_uint(a0)), "r"(__float_as_uint(a1)),                 \
          "r"(__float_as_uint(a2)), "r"(__float_as_uint(a3)),                 \
          "r"(__float_as_uint(b0)), "r"(__float_as_uint(b1)))

// ---------------- expert compute (tf32 mma.sync): tile = (slot, expert, 32 tokens) ----
// Both slots in ONE launch (slot0 -> out, slot1 -> g_extra); no atomics.
// Phase 1: A = gate*relu(H @ W1[e]) (32x64): M=32 (2 m-tiles), N=64, K=1024 in 32-chunks,
//          ping-pong SMEM + register prefetch (R11 pattern).
// Phase 2: O = A @ W2[e] (32x1024): A-fragments register-resident (K=64), W2 in 64-col tiles.
// Warp w: m-tile = w&1 (rows 16*(w&1)..+15), n-group = w>>1 (16 cols: two n8 tiles).
__global__ void __launch_bounds__(256, 3)
expert_kernel(const float* __restrict__ h,
              const float* __restrict__ W1,
              const float* __restrict__ W2,
              float* __restrict__ out)
{
    __shared__ __align__(16) float s_h[2 * 32 * 36];  // H chunk ping-pong: [b][t][k], stride 36
    __shared__ __align__(16) float s_w[4608];         // ph1: 2 bufs 32x72; ph2: one 64x72
    __shared__ __align__(16) float s_at[32 * 72];     // A: [t][k], stride 72 (tf32-rounded)
    __shared__ int   tok_s[TILE_T];
    __shared__ float gsc[TILE_T];

    int tid  = threadIdx.x;
    int warp = tid >> 5, lane = tid & 31;
    int mb   = (warp & 1) * 16;      // m-tile base row
    int ng   = warp >> 1;            // n-group (0..3): cols 16*ng .. +15
    int qr   = lane >> 2;            // 0..7
    int qc   = lane & 3;             // 0..3

    // fill maps
    int fh_t = tid >> 5;             // token (+8i, i<4) for H fill
    int fh_k = tid & 31;             // k within chunk
    int fw_r = tid >> 6;             // row (+4i) for W fills (64-wide)
    int fw_c = tid & 63;

    int nt0 = g_ntiles[0];
    int ntt = nt0 + g_ntiles[1];

    for (int tile = blockIdx.x; tile < ntt; tile += gridDim.x) {
        int slot = (tile >= nt0) ? 1 : 0;
        int tloc = slot ? tile - nt0 : tile;
        int desc = g_tiles[slot][tloc];
        int e  = desc >> 16;
        int ti = desc & 0xFFFF;
        int cnt_e = g_cnt[slot][e];
        int base  = g_off[slot][e] + ti * TILE_T;
        int nv = cnt_e - ti * TILE_T;
        if (nv > TILE_T) nv = TILE_T;

        if (tid < TILE_T) {
            int rr = tid < nv ? tid : (nv - 1);   // clamp; invalid rows masked at store
            tok_s[tid] = g_tok[slot][base + rr];
            gsc[tid]   = g_tg[slot][base + rr];
        }
        __syncthreads();

        const float* W1e = W1 + (size_t)e * DDIM * RRANK;

        // H row pointers for this thread's 4 fill tokens (fh_t + 8i)
        const float* hp0 = h + (size_t)tok_s[fh_t +  0] * DDIM + fh_k;
        const float* hp1 = h + (size_t)tok_s[fh_t +  8] * DDIM + fh_k;
        const float* hp2 = h + (size_t)tok_s[fh_t + 16] * DDIM + fh_k;
        const float* hp3 = h + (size_t)tok_s[fh_t + 24] * DDIM + fh_k;

        float hr[4], wr[8];
        // preload k-chunk 0
        hr[0] = hp0[0]; hr[1] = hp1[0]; hr[2] = hp2[0]; hr[3] = hp3[0];
#pragma unroll
        for (int i = 0; i < 8; i++)
            wr[i] = W1e[(size_t)(fw_r + 4 * i) * RRANK + fw_c];
        // store buf 0 (tf32-rounded)
        s_h[(fh_t +  0) * 36 + fh_k] = to_tf32(hr[0]);
        s_h[(fh_t +  8) * 36 + fh_k] = to_tf32(hr[1]);
        s_h[(fh_t + 16) * 36 + fh_k] = to_tf32(hr[2]);
        s_h[(fh_t + 24) * 36 + fh_k] = to_tf32(hr[3]);
#pragma unroll
        for (int i = 0; i < 8; i++)
            s_w[(fw_r + 4 * i) * 72 + fw_c] = to_tf32(wr[i]);
        __syncthreads();

        // ---------------- phase 1 ----------------
        float d1[2][4];
#pragma unroll
        for (int nt = 0; nt < 2; nt++)
#pragma unroll
            for (int j = 0; j < 4; j++) d1[nt][j] = 0.f;

        for (int kt = 0; kt < DDIM / 32; kt++) {
            int b = kt & 1;
            if (kt < DDIM / 32 - 1) {
                int k0 = (kt + 1) * 32;
                hr[0] = hp0[k0]; hr[1] = hp1[k0]; hr[2] = hp2[k0]; hr[3] = hp3[k0];
#pragma unroll
                for (int i = 0; i < 8; i++)
                    wr[i] = W1e[(size_t)(k0 + fw_r + 4 * i) * RRANK + fw_c];
            }
            const float* hb = s_h + b * 1152;
            const float* wb = s_w + b * 2304;
#pragma unroll
            for (int ks = 0; ks < 4; ks++) {
                int k0 = 8 * ks;
                float a0 = hb[(mb + qr) * 36 + k0 + qc];
                float a1 = hb[(mb + qr + 8) * 36 + k0 + qc];
                float a2 = hb[(mb + qr) * 36 + k0 + qc + 4];
                float a3 = hb[(mb + qr + 8) * 36 + k0 + qc + 4];
#pragma unroll
                for (int nt = 0; nt < 2; nt++) {
                    int n0 = 16 * ng + 8 * nt;
                    float b0 = wb[(k0 + qc) * 72 + n0 + qr];
                    float b1 = wb[(k0 + qc + 4) * 72 + n0 + qr];
                    MMA_TF32(d1[nt], a0, a1, a2, a3, b0, b1);
                }
            }
            if (kt < DDIM / 32 - 1) {
                int nb = 1 - b;
                s_h[nb * 1152 + (fh_t +  0) * 36 + fh_k] = to_tf32(hr[0]);
                s_h[nb * 1152 + (fh_t +  8) * 36 + fh_k] = to_tf32(hr[1]);
                s_h[nb * 1152 + (fh_t + 16) * 36 + fh_k] = to_tf32(hr[2]);
                s_h[nb * 1152 + (fh_t + 24) * 36 + fh_k] = to_tf32(hr[3]);
#pragma unroll
                for (int i = 0; i < 8; i++)
                    s_w[nb * 2304 + (fw_r + 4 * i) * 72 + fw_c] = to_tf32(wr[i]);
            }
            __syncthreads();
        }

        // ---------------- epilogue 1: relu*gate -> s_at; prefetch W2 ct0 ----------------
        const float* W2e = W2 + (size_t)e * RRANK * DDIM;
        float wr2[16];
#pragma unroll
        for (int i = 0; i < 16; i++)
            wr2[i] = W2e[(size_t)(fw_r + 4 * i) * DDIM + fw_c];

        {
            float glo = gsc[mb + qr], ghi = gsc[mb + qr + 8];
#pragma unroll
            for (int nt = 0; nt < 2; nt++) {
                int col = 16 * ng + 8 * nt + 2 * qc;
                float2 lo, hi;
                lo.x = to_tf32(fmaxf(d1[nt][0], 0.f) * glo);
                lo.y = to_tf32(fmaxf(d1[nt][1], 0.f) * glo);
                hi.x = to_tf32(fmaxf(d1[nt][2], 0.f) * ghi);
                hi.y = to_tf32(fmaxf(d1[nt][3], 0.f) * ghi);
                *(float2*)&s_at[(mb + qr) * 72 + col]     = lo;
                *(float2*)&s_at[(mb + qr + 8) * 72 + col] = hi;
            }
        }
        // W2 ct0 into s_w (phase-1 buffers dead after last barrier above)
#pragma unroll
        for (int i = 0; i < 16; i++)
            s_w[(fw_r + 4 * i) * 72 + fw_c] = to_tf32(wr2[i]);
        __syncthreads();

        // ---------------- phase 2: A-fragments resident, W2 64-col tiles ----------------
        float af[8][4];
#pragma unroll
        for (int ks = 0; ks < 8; ks++) {
            int k0 = 8 * ks;
            af[ks][0] = s_at[(mb + qr) * 72 + k0 + qc];
            af[ks][1] = s_at[(mb + qr + 8) * 72 + k0 + qc];
            af[ks][2] = s_at[(mb + qr) * 72 + k0 + qc + 4];
            af[ks][3] = s_at[(mb + qr + 8) * 72 + k0 + qc + 4];
        }

        int rlo = mb + qr, rhi = rlo + 8;
        bool vlo = rlo < nv, vhi = rhi < nv;
        size_t olo = (size_t)tok_s[rlo] * DDIM;
        size_t ohi = (size_t)tok_s[rhi] * DDIM;
        float* dst = slot ? g_extra : out;

        for (int ct = 0; ct < 16; ct++) {
            if (ct < 15) {
                int c0 = (ct + 1) * 64;
#pragma unroll
                for (int i = 0; i < 16; i++)
                    wr2[i] = W2e[(size_t)(fw_r + 4 * i) * DDIM + c0 + fw_c];
            }
            float d2[2][4];
#pragma unroll
            for (int nt = 0; nt < 2; nt++)
#pragma unroll
                for (int j = 0; j < 4; j++) d2[nt][j] = 0.f;
#pragma unroll
            for (int ks = 0; ks < 8; ks++) {
                int k0 = 8 * ks;
#pragma unroll
                for (int nt = 0; nt < 2; nt++) {
                    int n0 = 16 * ng + 8 * nt;
                    float b0 = s_w[(k0 + qc) * 72 + n0 + qr];
                    float b1 = s_w[(k0 + qc + 4) * 72 + n0 + qr];
                    MMA_TF32(d2[nt], af[ks][0], af[ks][1], af[ks][2], af[ks][3], b0, b1);
                }
            }
#pragma unroll
            for (int nt = 0; nt < 2; nt++) {
                int c = 64 * ct + 16 * ng + 8 * nt + 2 * qc;
                if (vlo) *(float2*)&dst[olo + c] = make_float2(d2[nt][0], d2[nt][1]);
                if (vhi) *(float2*)&dst[ohi + c] = make_float2(d2[nt][2], d2[nt][3]);
            }
            __syncthreads();     // all reads of s_w done (last iter: also s_at/tok_s)
            if (ct < 15) {
#pragma unroll
                for (int i = 0; i < 16; i++)
                    s_w[(fw_r + 4 * i) * 72 + fw_c] = to_tf32(wr2[i]);
                __syncthreads();
            }
        }
    }
}

// ---------------- merge: out += g_extra ----------------
__global__ void add_kernel(float* __restrict__ out, int n4) {
    int i = blockIdx.x * blockDim.x + threadIdx.x;
    int stride = gridDim.x * blockDim.x;
    const float4* ex = (const float4*)g_extra;
    float4* o = (float4*)out;
    for (; i < n4; i += stride) {
        float4 a = o[i], b = ex[i];
        a.x += b.x; a.y += b.y; a.z += b.z; a.w += b.w;
        o[i] = a;
    }
}

// ---------------- launch ----------------
extern "C" void kernel_launch(void* const* d_in, const int* in_sizes, int n_in,
                              void* d_out, int out_size)
{
    const float* h    = (const float*)d_in[0];
    const float* Wg   = (const float*)d_in[1];
    const float* bg   = (const float*)d_in[2];
    const float* Wloc = (const float*)d_in[3];
    const float* W1   = (const float*)d_in[4];
    const float* W2   = (const float*)d_in[5];

    int n = in_sizes[0] / DDIM;                 // 8192
    if (n > NTOK) n = NTOK;

    float* out = (float*)d_out;

    // Optional concatenated tail outputs: out(N*D), expert_ids(2N), gate(2N), group_idx(N)
    size_t need = (size_t)n * DDIM + 5 * (size_t)n;
    float* o_eid  = nullptr;
    float* o_gate = nullptr;
    float* o_grp  = nullptr;
    if ((size_t)out_size >= need) {
        o_eid  = out + (size_t)n * DDIM;
        o_gate = o_eid + 2 * (size_t)n;
        o_grp  = o_gate + 2 * (size_t)n;
    }

    init_kernel<<<1, 128>>>();
    routing_kernel<<<(n + 7) / 8, 256>>>(h, Wg, bg, Wloc, o_eid, o_gate, o_grp, n);
    prefix_kernel<<<1, 32>>>();
    scatter_kernel<<<(n + 255) / 256, 256>>>(n);
    // Both slots in one wave: slot0 tiles write `out`, slot1 tiles write g_extra
    expert_kernel<<<592, 256>>>(h, W1, W2, out);
    // out += g_extra
    add_kernel<<<1024, 256>>>(out, n * DDIM / 4);
}

// round 15
// speedup vs baseline: 1.6633x; 1.0120x over previous
#include <cuda_runtime.h>
#include <math.h>

// Problem constants (fixed-shape problem)
#define NTOK  8192
#define DDIM  1024
#define EEXP  64
#define RRANK 64
#define GGRP  8
#define MLOC  8

#define TILE_T 64           // tokens per expert tile
#define MAX_TILES 512       // per slot: <= N/TILE_T + E = 192

// ---------------- scratch (device globals; no allocations) ----------------
__device__ int   g_eid[NTOK * 2];      // global expert id per (token, slot)
__device__ float g_gate2[NTOK * 2];    // gate per (token, slot)
__device__ int   g_cnt[2][EEXP];
__device__ int   g_off[2][EEXP];
__device__ int   g_fill[2][EEXP];
__device__ int   g_tok[2][NTOK];       // token index, grouped by expert, per slot
__device__ float g_tg[2][NTOK];        // matching gate
__device__ int   g_tiles[2][MAX_TILES];// packed: (e<<16) | tile_index_within_expert
__device__ int   g_ntiles[2];
__device__ float g_extra[NTOK * DDIM]; // slot-1 partial output (merged by add_kernel)

// ---------------- init: zero counters ----------------
__global__ void init_kernel() {
    int t = threadIdx.x;
    if (t < EEXP) {
        g_cnt[0][t] = 0; g_cnt[1][t] = 0;
        g_fill[0][t] = 0; g_fill[1][t] = 0;
    }
    if (t == 0) { g_ntiles[0] = 0; g_ntiles[1] = 0; }
}

// ---------------- routing: one warp per token (unchanged, verified) ----------------
__global__ void routing_kernel(const float* __restrict__ h,
                               const float* __restrict__ Wg,
                               const float* __restrict__ bg,
                               const float* __restrict__ Wloc,
                               float* __restrict__ o_eid,    // may be null
                               float* __restrict__ o_gate,   // may be null
                               float* __restrict__ o_grp,    // may be null
                               int n)
{
    int warp = (blockIdx.x * blockDim.x + threadIdx.x) >> 5;
    int lane = threadIdx.x & 31;
    if (warp >= n) return;

    const float* hrow = h + (size_t)warp * DDIM;

    float hv[32];
#pragma unroll
    for (int i = 0; i < 32; i++) hv[i] = hrow[i * 32 + lane];

    // ---- stage 1: group scores (G=8) ----
    float sg[GGRP];
#pragma unroll
    for (int g = 0; g < GGRP; g++) sg[g] = 0.f;
#pragma unroll
    for (int i = 0; i < 32; i++) {
        int d = i * 32 + lane;
        const float4* wp = (const float4*)(Wg + (size_t)d * GGRP);
        float4 wa = wp[0], wb = wp[1];
        float x = hv[i];
        sg[0] += x * wa.x; sg[1] += x * wa.y; sg[2] += x * wa.z; sg[3] += x * wa.w;
        sg[4] += x * wb.x; sg[5] += x * wb.y; sg[6] += x * wb.z; sg[7] += x * wb.w;
    }
#pragma unroll
    for (int g = 0; g < GGRP; g++) {
#pragma unroll
        for (int off = 16; off > 0; off >>= 1)
            sg[g] += __shfl_xor_sync(0xFFFFFFFFu, sg[g], off);
        sg[g] += bg[g];
    }
    int gi = 0; float best = sg[0];
#pragma unroll
    for (int g = 1; g < GGRP; g++) if (sg[g] > best) { best = sg[g]; gi = g; }

    // ---- stage 2: local scores for selected group (M=8) ----
    float sl[MLOC];
#pragma unroll
    for (int m = 0; m < MLOC; m++) sl[m] = 0.f;
    const float* wl = Wloc + (size_t)gi * DDIM * MLOC;
#pragma unroll
    for (int i = 0; i < 32; i++) {
        int d = i * 32 + lane;
        const float4* wp = (const float4*)(wl + (size_t)d * MLOC);
        float4 wa = wp[0], wb = wp[1];
        float x = hv[i];
        sl[0] += x * wa.x; sl[1] += x * wa.y; sl[2] += x * wa.z; sl[3] += x * wa.w;
        sl[4] += x * wb.x; sl[5] += x * wb.y; sl[6] += x * wb.z; sl[7] += x * wb.w;
    }
#pragma unroll
    for (int m = 0; m < MLOC; m++) {
#pragma unroll
        for (int off = 16; off > 0; off >>= 1)
            sl[m] += __shfl_xor_sync(0xFFFFFFFFu, sl[m], off);
    }
    int m1 = 0; float v1 = sl[0];
#pragma unroll
    for (int m = 1; m < MLOC; m++) if (sl[m] > v1) { v1 = sl[m]; m1 = m; }
    int m2 = -1; float v2 = -INFINITY;
#pragma unroll
    for (int m = 0; m < MLOC; m++) if (m != m1 && sl[m] > v2) { v2 = sl[m]; m2 = m; }

    float e2 = expf(v2 - v1);
    float inv = 1.0f / (1.0f + e2);
    float gate0 = inv;
    float gate1 = e2 * inv;

    int eid0 = gi * MLOC + m1;
    int eid1 = gi * MLOC + m2;

    if (lane == 0) {
        g_eid[2 * warp + 0] = eid0;
        g_eid[2 * warp + 1] = eid1;
        g_gate2[2 * warp + 0] = gate0;
        g_gate2[2 * warp + 1] = gate1;
        atomicAdd(&g_cnt[0][eid0], 1);
        atomicAdd(&g_cnt[1][eid1], 1);
        if (o_eid)  { o_eid[2 * warp + 0] = (float)eid0; o_eid[2 * warp + 1] = (float)eid1; }
        if (o_gate) { o_gate[2 * warp + 0] = gate0;      o_gate[2 * warp + 1] = gate1; }
        if (o_grp)  { o_grp[warp] = (float)gi; }
    }
}

// ---------------- prefix sums + tile lists (tiny; single thread) ----------------
__global__ void prefix_kernel() {
    if (threadIdx.x != 0 || blockIdx.x != 0) return;
#pragma unroll
    for (int s = 0; s < 2; s++) {
        int acc = 0, nt = 0;
        for (int e = 0; e < EEXP; e++) {
            g_off[s][e] = acc;
            int c = g_cnt[s][e];
            acc += c;
            int t = (c + TILE_T - 1) / TILE_T;
            for (int i = 0; i < t && nt < MAX_TILES; i++)
                g_tiles[s][nt++] = (e << 16) | i;
        }
        g_ntiles[s] = nt;
    }
}

// ---------------- scatter tokens into per-expert, per-slot buckets ----------------
__global__ void scatter_kernel(int n) {
    int t = blockIdx.x * blockDim.x + threadIdx.x;
    if (t >= n) return;
#pragma unroll
    for (int j = 0; j < 2; j++) {
        int e = g_eid[2 * t + j];
        int p = g_off[j][e] + atomicAdd(&g_fill[j][e], 1);
        g_tok[j][p] = t;
        g_tg[j][p]  = g_gate2[2 * t + j];
    }
}

// ---------------- tf32 helpers ----------------
__device__ __forceinline__ float to_tf32(float x) {
    float y;
    asm("cvt.rna.tf32.f32 %0, %1;" : "=f"(y) : "f"(x));
    return y;
}

#define MMA_TF32(d, a0, a1, a2, a3, b0, b1)                                   \
    asm volatile(                                                             \
        "mma.sync.aligned.m16n8k8.row.col.f32.tf32.tf32.f32 "                 \
        "{%0,%1,%2,%3}, {%4,%5,%6,%7}, {%8,%9}, {%0,%1,%2,%3};"               \
        : "+f"((d)[0]), "+f"((d)[1]), "+f"((d)[2]), "+f"((d)[3])              \
        : "r"(__float_as_uint(a0)), "r"(__float_as_uint(a1)),                 \
          "r"(__float_as_uint(a2)), "r"(__float_as_uint(a3)),                 \
          "r"(__float_as_uint(b0)), "r"(__float_as_uint(b1)))

// ---------------- expert compute (tf32 mma.sync): tile = (slot, expert, 64 tokens) ----
// Both slots in ONE launch (slot0 -> out, slot1 -> g_extra); no atomics.
// Phase 1: A = gate*relu(H @ W1[e]) (64x64): K=1024 in 32-chunks, ping-pong + reg-prefetch.
// Phase 2: O = A @ W2[e] (64x1024): A-fragments register-resident, W2 in 64-col tiles.
// Warp w (8 warps): m-tile = w&3 (rows 16*(w&3)..+15), n-group = w>>2 (32 cols: 4 n8 tiles).
__global__ void __launch_bounds__(256, 2)
expert_kernel(const float* __restrict__ h,
              const float* __restrict__ W1,
              const float* __restrict__ W2,
              float* __restrict__ out)
{
    // s_u: phase1 H chunk ping-pong, [b][t][k] stride 36 (2 x 2304 floats)
    //      phase2 A, [t][k] stride 72 (4608 floats) — aliased
    __shared__ __align__(16) float s_u[4608];
    // s_w: phase1 W1 ping-pong [b][k][n] stride 72 (2 x 2304); phase2 W2 [k][n] stride 72 (4608)
    __shared__ __align__(16) float s_w[4608];
    __shared__ int   tok_s[TILE_T];
    __shared__ float gsc[TILE_T];

    int tid  = threadIdx.x;
    int warp = tid >> 5, lane = tid & 31;
    int mb   = (warp & 3) * 16;      // m-tile base row
    int ng   = warp >> 2;            // n-group (0..1): cols 32*ng .. +31
    int qr   = lane >> 2;            // 0..7
    int qc   = lane & 3;             // 0..3

    // fill maps
    int fh_t = tid >> 5;             // token (+8i, i<8) for H fill
    int fh_k = tid & 31;             // k within chunk
    int fw_r = tid >> 6;             // row (+4i) for W fills (64-wide)
    int fw_c = tid & 63;

    int nt0 = g_ntiles[0];
    int ntt = nt0 + g_ntiles[1];

    for (int tile = blockIdx.x; tile < ntt; tile += gridDim.x) {
        int slot = (tile >= nt0) ? 1 : 0;
        int tloc = slot ? tile - nt0 : tile;
        int desc = g_tiles[slot][tloc];
        int e  = desc >> 16;
        int ti = desc & 0xFFFF;
        int cnt_e = g_cnt[slot][e];
        int base  = g_off[slot][e] + ti * TILE_T;
        int nv = cnt_e - ti * TILE_T;
        if (nv > TILE_T) nv = TILE_T;

        if (tid < TILE_T) {
            int rr = tid < nv ? tid : (nv - 1);   // clamp; invalid rows masked at store
            tok_s[tid] = g_tok[slot][base + rr];
            gsc[tid]   = g_tg[slot][base + rr];
        }
        __syncthreads();

        const float* W1e = W1 + (size_t)e * DDIM * RRANK;

        // element offsets of this thread's 8 H-fill token rows (tokens fh_t + 8i)
        int hoff[8];
#pragma unroll
        for (int i = 0; i < 8; i++) hoff[i] = tok_s[fh_t + 8 * i] * DDIM;

        float hr[8], wr[8];
        // preload k-chunk 0
#pragma unroll
        for (int i = 0; i < 8; i++) hr[i] = h[(size_t)hoff[i] + fh_k];
#pragma unroll
        for (int i = 0; i < 8; i++) wr[i] = W1e[(size_t)(fw_r + 4 * i) * RRANK + fw_c];
        // store buf 0 (tf32-rounded)
#pragma unroll
        for (int i = 0; i < 8; i++) s_u[(fh_t + 8 * i) * 36 + fh_k] = to_tf32(hr[i]);
#pragma unroll
        for (int i = 0; i < 8; i++) s_w[(fw_r + 4 * i) * 72 + fw_c] = to_tf32(wr[i]);
        __syncthreads();

        // ---------------- phase 1 ----------------
        float d1[4][4];
#pragma unroll
        for (int nt = 0; nt < 4; nt++)
#pragma unroll
            for (int j = 0; j < 4; j++) d1[nt][j] = 0.f;

        for (int kt = 0; kt < DDIM / 32; kt++) {
            int b = kt & 1;
            if (kt < DDIM / 32 - 1) {
                int k0 = (kt + 1) * 32;
#pragma unroll
                for (int i = 0; i < 8; i++) hr[i] = h[(size_t)hoff[i] + k0 + fh_k];
#pragma unroll
                for (int i = 0; i < 8; i++)
                    wr[i] = W1e[(size_t)(k0 + fw_r + 4 * i) * RRANK + fw_c];
            }
            const float* hb = s_u + b * 2304;
            const float* wb = s_w + b * 2304;
#pragma unroll
            for (int ks = 0; ks < 4; ks++) {
                int k0 = 8 * ks;
                float a0 = hb[(mb + qr) * 36 + k0 + qc];
                float a1 = hb[(mb + qr + 8) * 36 + k0 + qc];
                float a2 = hb[(mb + qr) * 36 + k0 + qc + 4];
                float a3 = hb[(mb + qr + 8) * 36 + k0 + qc + 4];
#pragma unroll
                for (int nt = 0; nt < 4; nt++) {
                    int n0 = 32 * ng + 8 * nt;
                    float b0 = wb[(k0 + qc) * 72 + n0 + qr];
                    float b1 = wb[(k0 + qc + 4) * 72 + n0 + qr];
                    MMA_TF32(d1[nt], a0, a1, a2, a3, b0, b1);
                }
            }
            if (kt < DDIM / 32 - 1) {
                int nb = 1 - b;
#pragma unroll
                for (int i = 0; i < 8; i++)
                    s_u[nb * 2304 + (fh_t + 8 * i) * 36 + fh_k] = to_tf32(hr[i]);
#pragma unroll
                for (int i = 0; i < 8; i++)
                    s_w[nb * 2304 + (fw_r + 4 * i) * 72 + fw_c] = to_tf32(wr[i]);
            }
            __syncthreads();
        }

        // ---------------- epilogue 1: relu*gate -> A (aliases s_u); prefetch W2 ct0 ----
        const float* W2e = W2 + (size_t)e * RRANK * DDIM;
        float wr2[16];
#pragma unroll
        for (int i = 0; i < 16; i++)
            wr2[i] = W2e[(size_t)(fw_r + 4 * i) * DDIM + fw_c];

        {
            float glo = gsc[mb + qr], ghi = gsc[mb + qr + 8];
#pragma unroll
            for (int nt = 0; nt < 4; nt++) {
                int col = 32 * ng + 8 * nt + 2 * qc;
                float2 lo, hi;
                lo.x = to_tf32(fmaxf(d1[nt][0], 0.f) * glo);
                lo.y = to_tf32(fmaxf(d1[nt][1], 0.f) * glo);
                hi.x = to_tf32(fmaxf(d1[nt][2], 0.f) * ghi);
                hi.y = to_tf32(fmaxf(d1[nt][3], 0.f) * ghi);
                *(float2*)&s_u[(mb + qr) * 72 + col]     = lo;
                *(float2*)&s_u[(mb + qr + 8) * 72 + col] = hi;
            }
        }
        // W2 ct0 into s_w (phase-1 buffers dead after last barrier above)
#pragma unroll
        for (int i = 0; i < 16; i++)
            s_w[(fw_r + 4 * i) * 72 + fw_c] = to_tf32(wr2[i]);
        __syncthreads();

        // ---------------- phase 2: A-fragments resident, W2 64-col tiles ----------------
        float af[8][4];
#pragma unroll
        for (int ks = 0; ks < 8; ks++) {
            int k0 = 8 * ks;
            af[ks][0] = s_u[(mb + qr) * 72 + k0 + qc];
            af[ks][1] = s_u[(mb + qr + 8) * 72 + k0 + qc];
            af[ks][2] = s_u[(mb + qr) * 72 + k0 + qc + 4];
            af[ks][3] = s_u[(mb + qr + 8) * 72 + k0 + qc + 4];
        }

        int rlo = mb + qr, rhi = rlo + 8;
        bool vlo = rlo < nv, vhi = rhi < nv;
        size_t olo = (size_t)tok_s[rlo] * DDIM;
        size_t ohi = (size_t)tok_s[rhi] * DDIM;
        float* dst = slot ? g_extra : out;

        for (int ct = 0; ct < 16; ct++) {
            if (ct < 15) {
                int c0 = (ct + 1) * 64;
#pragma unroll
                for (int i = 0; i < 16; i++)
                    wr2[i] = W2e[(size_t)(fw_r + 4 * i) * DDIM + c0 + fw_c];
            }
            float d2[4][4];
#pragma unroll
            for (int nt = 0; nt < 4; nt++)
#pragma unroll
                for (int j = 0; j < 4; j++) d2[nt][j] = 0.f;
#pragma unroll
            for (int ks = 0; ks < 8; ks++) {
                int k0 = 8 * ks;
#pragma unroll
                for (int nt = 0; nt < 4; nt++) {
                    int n0 = 32 * ng + 8 * nt;
                    float b0 = s_w[(k0 + qc) * 72 + n0 + qr];
                    float b1 = s_w[(k0 + qc + 4) * 72 + n0 + qr];
                    MMA_TF32(d2[nt], af[ks][0], af[ks][1], af[ks][2], af[ks][3], b0, b1);
                }
            }
#pragma unroll
            for (int nt = 0; nt < 4; nt++) {
                int c = 64 * ct + 32 * ng + 8 * nt + 2 * qc;
                if (vlo) *(float2*)&dst[olo + c] = make_float2(d2[nt][0], d2[nt][1]);
                if (vhi) *(float2*)&dst[ohi + c] = make_float2(d2[nt][2], d2[nt][3]);
            }
            __syncthreads();     // all reads of s_w done (last iter: also s_u/tok_s)
            if (ct < 15) {
#pragma unroll
                for (int i = 0; i < 16; i++)
                    s_w[(fw_r + 4 * i) * 72 + fw_c] = to_tf32(wr2[i]);
                __syncthreads();
            }
        }
    }
}

// ---------------- merge: out += g_extra ----------------
__global__ void add_kernel(float* __restrict__ out, int n4) {
    int i = blockIdx.x * blockDim.x + threadIdx.x;
    int stride = gridDim.x * blockDim.x;
    const float4* ex = (const float4*)g_extra;
    float4* o = (float4*)out;
    for (; i < n4; i += stride) {
        float4 a = o[i], b = ex[i];
        a.x += b.x; a.y += b.y; a.z += b.z; a.w += b.w;
        o[i] = a;
    }
}

// ---------------- launch ----------------
extern "C" void kernel_launch(void* const* d_in, const int* in_sizes, int n_in,
                              void* d_out, int out_size)
{
    const float* h    = (const float*)d_in[0];
    const float* Wg   = (const float*)d_in[1];
    const float* bg   = (const float*)d_in[2];
    const float* Wloc = (const float*)d_in[3];
    const float* W1   = (const float*)d_in[4];
    const float* W2   = (const float*)d_in[5];

    int n = in_sizes[0] / DDIM;                 // 8192
    if (n > NTOK) n = NTOK;

    float* out = (float*)d_out;

    // Optional concatenated tail outputs: out(N*D), expert_ids(2N), gate(2N), group_idx(N)
    size_t need = (size_t)n * DDIM + 5 * (size_t)n;
    float* o_eid  = nullptr;
    float* o_gate = nullptr;
    float* o_grp  = nullptr;
    if ((size_t)out_size >= need) {
        o_eid  = out + (size_t)n * DDIM;
        o_gate = o_eid + 2 * (size_t)n;
        o_grp  = o_gate + 2 * (size_t)n;
    }

    init_kernel<<<1, 128>>>();
    routing_kernel<<<(n + 7) / 8, 256>>>(h, Wg, bg, Wloc, o_eid, o_gate, o_grp, n);
    prefix_kernel<<<1, 32>>>();
    scatter_kernel<<<(n + 255) / 256, 256>>>(n);
    // Both slots in one wave: slot0 tiles write `out`, slot1 tiles write g_extra
    expert_kernel<<<384, 256>>>(h, W1, W2, out);
    // out += g_extra
    add_kernel<<<1024, 256>>>(out, n * DDIM / 4);
}

// round 16
// speedup vs baseline: 1.8267x; 1.0982x over previous
#include <cuda_runtime.h>
#include <math.h>

// Problem constants (fixed-shape problem)
#define NTOK  8192
#define DDIM  1024
#define EEXP  64
#define RRANK 64
#define GGRP  8
#define MLOC  8

#define TILE_T 64           // tokens per expert tile
#define MAX_TILES 512       // per slot: <= N/TILE_T + E = 192

// ---------------- scratch (device globals; no allocations) ----------------
__device__ int   g_eid[NTOK * 2];      // global expert id per (token, slot)
__device__ float g_gate2[NTOK * 2];    // gate per (token, slot)
__device__ int   g_cnt[2][EEXP];
__device__ int   g_off[2][EEXP];
__device__ int   g_fill[2][EEXP];
__device__ int   g_tok[2][NTOK];       // token index, grouped by expert, per slot
__device__ float g_tg[2][NTOK];        // matching gate
__device__ int   g_tiles[2][MAX_TILES];// packed: (e<<16) | tile_index_within_expert
__device__ int   g_ntiles[2];
__device__ float g_extra[NTOK * DDIM]; // slot-1 partial output (merged by add_kernel)

// ---------------- init: zero counters ----------------
__global__ void init_kernel() {
    int t = threadIdx.x;
    if (t < EEXP) {
        g_cnt[0][t] = 0; g_cnt[1][t] = 0;
        g_fill[0][t] = 0; g_fill[1][t] = 0;
    }
    if (t == 0) { g_ntiles[0] = 0; g_ntiles[1] = 0; }
}

// ---------------- routing: one warp per token (unchanged, verified) ----------------
__global__ void routing_kernel(const float* __restrict__ h,
                               const float* __restrict__ Wg,
                               const float* __restrict__ bg,
                               const float* __restrict__ Wloc,
                               float* __restrict__ o_eid,    // may be null
                               float* __restrict__ o_gate,   // may be null
                               float* __restrict__ o_grp,    // may be null
                               int n)
{
    int warp = (blockIdx.x * blockDim.x + threadIdx.x) >> 5;
    int lane = threadIdx.x & 31;
    if (warp >= n) return;

    const float* hrow = h + (size_t)warp * DDIM;

    float hv[32];
#pragma unroll
    for (int i = 0; i < 32; i++) hv[i] = hrow[i * 32 + lane];

    // ---- stage 1: group scores (G=8) ----
    float sg[GGRP];
#pragma unroll
    for (int g = 0; g < GGRP; g++) sg[g] = 0.f;
#pragma unroll
    for (int i = 0; i < 32; i++) {
        int d = i * 32 + lane;
        const float4* wp = (const float4*)(Wg + (size_t)d * GGRP);
        float4 wa = wp[0], wb = wp[1];
        float x = hv[i];
        sg[0] += x * wa.x; sg[1] += x * wa.y; sg[2] += x * wa.z; sg[3] += x * wa.w;
        sg[4] += x * wb.x; sg[5] += x * wb.y; sg[6] += x * wb.z; sg[7] += x * wb.w;
    }
#pragma unroll
    for (int g = 0; g < GGRP; g++) {
#pragma unroll
        for (int off = 16; off > 0; off >>= 1)
            sg[g] += __shfl_xor_sync(0xFFFFFFFFu, sg[g], off);
        sg[g] += bg[g];
    }
    int gi = 0; float best = sg[0];
#pragma unroll
    for (int g = 1; g < GGRP; g++) if (sg[g] > best) { best = sg[g]; gi = g; }

    // ---- stage 2: local scores for selected group (M=8) ----
    float sl[MLOC];
#pragma unroll
    for (int m = 0; m < MLOC; m++) sl[m] = 0.f;
    const float* wl = Wloc + (size_t)gi * DDIM * MLOC;
#pragma unroll
    for (int i = 0; i < 32; i++) {
        int d = i * 32 + lane;
        const float4* wp = (const float4*)(wl + (size_t)d * MLOC);
        float4 wa = wp[0], wb = wp[1];
        float x = hv[i];
        sl[0] += x * wa.x; sl[1] += x * wa.y; sl[2] += x * wa.z; sl[3] += x * wa.w;
        sl[4] += x * wb.x; sl[5] += x * wb.y; sl[6] += x * wb.z; sl[7] += x * wb.w;
    }
#pragma unroll
    for (int m = 0; m < MLOC; m++) {
#pragma unroll
        for (int off = 16; off > 0; off >>= 1)
            sl[m] += __shfl_xor_sync(0xFFFFFFFFu, sl[m], off);
    }
    int m1 = 0; float v1 = sl[0];
#pragma unroll
    for (int m = 1; m < MLOC; m++) if (sl[m] > v1) { v1 = sl[m]; m1 = m; }
    int m2 = -1; float v2 = -INFINITY;
#pragma unroll
    for (int m = 0; m < MLOC; m++) if (m != m1 && sl[m] > v2) { v2 = sl[m]; m2 = m; }

    float e2 = expf(v2 - v1);
    float inv = 1.0f / (1.0f + e2);
    float gate0 = inv;
    float gate1 = e2 * inv;

    int eid0 = gi * MLOC + m1;
    int eid1 = gi * MLOC + m2;

    if (lane == 0) {
        g_eid[2 * warp + 0] = eid0;
        g_eid[2 * warp + 1] = eid1;
        g_gate2[2 * warp + 0] = gate0;
        g_gate2[2 * warp + 1] = gate1;
        atomicAdd(&g_cnt[0][eid0], 1);
        atomicAdd(&g_cnt[1][eid1], 1);
        if (o_eid)  { o_eid[2 * warp + 0] = (float)eid0; o_eid[2 * warp + 1] = (float)eid1; }
        if (o_gate) { o_gate[2 * warp + 0] = gate0;      o_gate[2 * warp + 1] = gate1; }
        if (o_grp)  { o_grp[warp] = (float)gi; }
    }
}

// ---------------- prefix sums + tile lists (parallel: warp per slot) ----------------
// 64 threads: warp w = slot w; lane l handles experts {2l, 2l+1}.
__global__ void prefix_kernel() {
    int tid = threadIdx.x;
    if (tid >= 64) return;
    int s = tid >> 5;
    int l = tid & 31;
    int e0 = 2 * l, e1 = 2 * l + 1;

    int c0 = g_cnt[s][e0];
    int c1 = g_cnt[s][e1];

    // token-offset scan
    int pair = c0 + c1;
    int incl = pair;
#pragma unroll
    for (int off = 1; off < 32; off <<= 1) {
        int v = __shfl_up_sync(0xFFFFFFFFu, incl, off);
        if (l >= off) incl += v;
    }
    g_off[s][e0] = incl - pair;
    g_off[s][e1] = incl - c1;

    // tile-offset scan
    int t0 = (c0 + TILE_T - 1) / TILE_T;
    int t1 = (c1 + TILE_T - 1) / TILE_T;
    int tp = t0 + t1;
    int tincl = tp;
#pragma unroll
    for (int off = 1; off < 32; off <<= 1) {
        int v = __shfl_up_sync(0xFFFFFFFFu, tincl, off);
        if (l >= off) tincl += v;
    }
    int tb0 = tincl - tp;
    int tb1 = tincl - t1;
    for (int i = 0; i < t0; i++) g_tiles[s][tb0 + i] = (e0 << 16) | i;
    for (int i = 0; i < t1; i++) g_tiles[s][tb1 + i] = (e1 << 16) | i;
    if (l == 31) g_ntiles[s] = tincl;
}

// ---------------- scatter tokens into per-expert, per-slot buckets ----------------
// one thread per (token, slot) pair
__global__ void scatter_kernel(int n) {
    int i = blockIdx.x * blockDim.x + threadIdx.x;
    if (i >= 2 * n) return;
    int t = i >> 1, j = i & 1;
    int e = g_eid[2 * t + j];
    int p = g_off[j][e] + atomicAdd(&g_fill[j][e], 1);
    g_tok[j][p] = t;
    g_tg[j][p]  = g_gate2[2 * t + j];
}

// ---------------- tf32 helpers ----------------
__device__ __forceinline__ float to_tf32(float x) {
    float y;
    asm("cvt.rna.tf32.f32 %0, %1;" : "=f"(y) : "f"(x));
    return y;
}

#define MMA_TF32(d, a0, a1, a2, a3, b0, b1)                                   \
    asm volatile(                                                             \
        "mma.sync.aligned.m16n8k8.row.col.f32.tf32.tf32.f32 "                 \
        "{%0,%1,%2,%3}, {%4,%5,%6,%7}, {%8,%9}, {%0,%1,%2,%3};"               \
        : "+f"((d)[0]), "+f"((d)[1]), "+f"((d)[2]), "+f"((d)[3])              \
        : "r"(__float_as_uint(a0)), "r"(__float_as_uint(a1)),                 \
          "r"(__float_as_uint(a2)), "r"(__float_as_uint(a3)),                 \
          "r"(__float_as_uint(b0)), "r"(__float_as_uint(b1)))

// ---------------- expert compute (tf32 mma.sync): tile = (slot, expert, 64 tokens) ----
// Both slots in ONE launch (slot0 -> out, slot1 -> g_extra); no atomics.
// Phase 1: A = gate*relu(H @ W1[e]) (64x64): K=1024 in 32-chunks, ping-pong + reg-prefetch.
// Phase 2: O = A @ W2[e] (64x1024): A-fragments register-resident; W2 64-col tiles
//          ping-ponged across s_w and s_u (A's SMEM is dead after fragment load) —
//          ONE barrier per column tile, STS overlapped with MMA.
// Warp w (8 warps): m-tile = w&3 (rows 16*(w&3)..+15), n-group = w>>2 (32 cols: 4 n8 tiles).
__global__ void __launch_bounds__(256, 2)
expert_kernel(const float* __restrict__ h,
              const float* __restrict__ W1,
              const float* __restrict__ W2,
              float* __restrict__ out)
{
    // s_u: phase1 H chunk ping-pong [b][t][k] stride 36 (2 x 2304 floats)
    //      epilogue A [t][k] stride 72; phase2 W2 buffer (odd ct) — all aliased
    __shared__ __align__(16) float s_u[4608];
    // s_w: phase1 W1 ping-pong [b][k][n] stride 72 (2 x 2304); phase2 W2 buffer (even ct)
    __shared__ __align__(16) float s_w[4608];
    __shared__ int   tok_s[TILE_T];
    __shared__ float gsc[TILE_T];

    int tid  = threadIdx.x;
    int warp = tid >> 5, lane = tid & 31;
    int mb   = (warp & 3) * 16;      // m-tile base row
    int ng   = warp >> 2;            // n-group (0..1): cols 32*ng .. +31
    int qr   = lane >> 2;            // 0..7
    int qc   = lane & 3;             // 0..3

    // fill maps
    int fh_t = tid >> 5;             // token (+8i, i<8) for H fill
    int fh_k = tid & 31;             // k within chunk
    int fw_r = tid >> 6;             // row (+4i) for W fills (64-wide)
    int fw_c = tid & 63;

    int nt0 = g_ntiles[0];
    int ntt = nt0 + g_ntiles[1];

    for (int tile = blockIdx.x; tile < ntt; tile += gridDim.x) {
        int slot = (tile >= nt0) ? 1 : 0;
        int tloc = slot ? tile - nt0 : tile;
        int desc = g_tiles[slot][tloc];
        int e  = desc >> 16;
        int ti = desc & 0xFFFF;
        int cnt_e = g_cnt[slot][e];
        int base  = g_off[slot][e] + ti * TILE_T;
        int nv = cnt_e - ti * TILE_T;
        if (nv > TILE_T) nv = TILE_T;

        if (tid < TILE_T) {
            int rr = tid < nv ? tid : (nv - 1);   // clamp; invalid rows masked at store
            tok_s[tid] = g_tok[slot][base + rr];
            gsc[tid]   = g_tg[slot][base + rr];
        }
        __syncthreads();

        const float* W1e = W1 + (size_t)e * DDIM * RRANK;

        // element offsets of this thread's 8 H-fill token rows (tokens fh_t + 8i)
        int hoff[8];
#pragma unroll
        for (int i = 0; i < 8; i++) hoff[i] = tok_s[fh_t + 8 * i] * DDIM;

        float hr[8], wr[8];
        // preload k-chunk 0
#pragma unroll
        for (int i = 0; i < 8; i++) hr[i] = h[(size_t)hoff[i] + fh_k];
#pragma unroll
        for (int i = 0; i < 8; i++) wr[i] = W1e[(size_t)(fw_r + 4 * i) * RRANK + fw_c];
        // store buf 0 (tf32-rounded)
#pragma unroll
        for (int i = 0; i < 8; i++) s_u[(fh_t + 8 * i) * 36 + fh_k] = to_tf32(hr[i]);
#pragma unroll
        for (int i = 0; i < 8; i++) s_w[(fw_r + 4 * i) * 72 + fw_c] = to_tf32(wr[i]);
        __syncthreads();

        // ---------------- phase 1 ----------------
        float d1[4][4];
#pragma unroll
        for (int nt = 0; nt < 4; nt++)
#pragma unroll
            for (int j = 0; j < 4; j++) d1[nt][j] = 0.f;

        for (int kt = 0; kt < DDIM / 32; kt++) {
            int b = kt & 1;
            if (kt < DDIM / 32 - 1) {
                int k0 = (kt + 1) * 32;
#pragma unroll
                for (int i = 0; i < 8; i++) hr[i] = h[(size_t)hoff[i] + k0 + fh_k];
#pragma unroll
                for (int i = 0; i < 8; i++)
                    wr[i] = W1e[(size_t)(k0 + fw_r + 4 * i) * RRANK + fw_c];
            }
            const float* hb = s_u + b * 2304;
            const float* wb = s_w + b * 2304;
#pragma unroll
            for (int ks = 0; ks < 4; ks++) {
                int k0 = 8 * ks;
                float a0 = hb[(mb + qr) * 36 + k0 + qc];
                float a1 = hb[(mb + qr + 8) * 36 + k0 + qc];
                float a2 = hb[(mb + qr) * 36 + k0 + qc + 4];
                float a3 = hb[(mb + qr + 8) * 36 + k0 + qc + 4];
#pragma unroll
                for (int nt = 0; nt < 4; nt++) {
                    int n0 = 32 * ng + 8 * nt;
                    float b0 = wb[(k0 + qc) * 72 + n0 + qr];
                    float b1 = wb[(k0 + qc + 4) * 72 + n0 + qr];
                    MMA_TF32(d1[nt], a0, a1, a2, a3, b0, b1);
                }
            }
            if (kt < DDIM / 32 - 1) {
                int nb = 1 - b;
#pragma unroll
                for (int i = 0; i < 8; i++)
                    s_u[nb * 2304 + (fh_t + 8 * i) * 36 + fh_k] = to_tf32(hr[i]);
#pragma unroll
                for (int i = 0; i < 8; i++)
                    s_w[nb * 2304 + (fw_r + 4 * i) * 72 + fw_c] = to_tf32(wr[i]);
            }
            __syncthreads();
        }

        // ---------------- epilogue 1: relu*gate -> A (aliases s_u); W2 ct0 -> s_w ----
        const float* W2e = W2 + (size_t)e * RRANK * DDIM;
        float wr2[16];
#pragma unroll
        for (int i = 0; i < 16; i++)
            wr2[i] = W2e[(size_t)(fw_r + 4 * i) * DDIM + fw_c];

        {
            float glo = gsc[mb + qr], ghi = gsc[mb + qr + 8];
#pragma unroll
            for (int nt = 0; nt < 4; nt++) {
                int col = 32 * ng + 8 * nt + 2 * qc;
                float2 lo, hi;
                lo.x = to_tf32(fmaxf(d1[nt][0], 0.f) * glo);
                lo.y = to_tf32(fmaxf(d1[nt][1], 0.f) * glo);
                hi.x = to_tf32(fmaxf(d1[nt][2], 0.f) * ghi);
                hi.y = to_tf32(fmaxf(d1[nt][3], 0.f) * ghi);
                *(float2*)&s_u[(mb + qr) * 72 + col]     = lo;
                *(float2*)&s_u[(mb + qr + 8) * 72 + col] = hi;
            }
        }
#pragma unroll
        for (int i = 0; i < 16; i++)
            s_w[(fw_r + 4 * i) * 72 + fw_c] = to_tf32(wr2[i]);
        __syncthreads();   // A + W2 ct0 visible

        // ---------------- phase 2: af resident; W2 ping-pong s_w/s_u -------------
        float af[8][4];
#pragma unroll
        for (int ks = 0; ks < 8; ks++) {
            int k0 = 8 * ks;
            af[ks][0] = s_u[(mb + qr) * 72 + k0 + qc];
            af[ks][1] = s_u[(mb + qr + 8) * 72 + k0 + qc];
            af[ks][2] = s_u[(mb + qr) * 72 + k0 + qc + 4];
            af[ks][3] = s_u[(mb + qr + 8) * 72 + k0 + qc + 4];
        }
        // prefetch W2 ct=1
#pragma unroll
        for (int i = 0; i < 16; i++)
            wr2[i] = W2e[(size_t)(fw_r + 4 * i) * DDIM + 64 + fw_c];
        __syncthreads();   // all af reads of s_u done — s_u becomes W2 odd buffer
#pragma unroll
        for (int i = 0; i < 16; i++)
            s_u[(fw_r + 4 * i) * 72 + fw_c] = to_tf32(wr2[i]);
        // (visibility of this STS to other warps is provided by the barrier at end of ct=0)

        int rlo = mb + qr, rhi = rlo + 8;
        bool vlo = rlo < nv, vhi = rhi < nv;
        size_t olo = (size_t)tok_s[rlo] * DDIM;
        size_t ohi = (size_t)tok_s[rhi] * DDIM;
        float* dst = slot ? g_extra : out;

        for (int ct = 0; ct < 16; ct++) {
            if (ct + 2 < 16) {
                int c0 = (ct + 2) * 64;
#pragma unroll
                for (int i = 0; i < 16; i++)
                    wr2[i] = W2e[(size_t)(fw_r + 4 * i) * DDIM + c0 + fw_c];
            }
            const float* wb = (ct & 1) ? s_u : s_w;
            float d2[4][4];
#pragma unroll
            for (int nt = 0; nt < 4; nt++)
#pragma unroll
                for (int j = 0; j < 4; j++) d2[nt][j] = 0.f;
#pragma unroll
            for (int ks = 0; ks < 8; ks++) {
                int k0 = 8 * ks;
#pragma unroll
                for (int nt = 0; nt < 4; nt++) {
                    int n0 = 32 * ng + 8 * nt;
                    float b0 = wb[(k0 + qc) * 72 + n0 + qr];
                    float b1 = wb[(k0 + qc + 4) * 72 + n0 + qr];
                    MMA_TF32(d2[nt], af[ks][0], af[ks][1], af[ks][2], af[ks][3], b0, b1);
                }
            }
#pragma unroll
            for (int nt = 0; nt < 4; nt++) {
                int c = 64 * ct + 32 * ng + 8 * nt + 2 * qc;
                if (vlo) *(float2*)&dst[olo + c] = make_float2(d2[nt][0], d2[nt][1]);
                if (vhi) *(float2*)&dst[ohi + c] = make_float2(d2[nt][2], d2[nt][3]);
            }
            __syncthreads();   // reads of wb done; STS for ct+1 (issued last iter) visible
            if (ct + 2 < 16) {
                float* sb = (ct & 1) ? s_u : s_w;   // buffer just freed this iteration
#pragma unroll
                for (int i = 0; i < 16; i++)
                    sb[(fw_r + 4 * i) * 72 + fw_c] = to_tf32(wr2[i]);
            }
        }
        __syncthreads();   // protect tok_s/gsc/smem reuse for next tile
    }
}

// ---------------- merge: out += g_extra ----------------
__global__ void add_kernel(float* __restrict__ out, int n4) {
    int i = blockIdx.x * blockDim.x + threadIdx.x;
    int stride = gridDim.x * blockDim.x;
    const float4* ex = (const float4*)g_extra;
    float4* o = (float4*)out;
    for (; i < n4; i += stride) {
        float4 a = o[i], b = ex[i];
        a.x += b.x; a.y += b.y; a.z += b.z; a.w += b.w;
        o[i] = a;
    }
}

// ---------------- launch ----------------
extern "C" void kernel_launch(void* const* d_in, const int* in_sizes, int n_in,
                              void* d_out, int out_size)
{
    const float* h    = (const float*)d_in[0];
    const float* Wg   = (const float*)d_in[1];
    const float* bg   = (const float*)d_in[2];
    const float* Wloc = (const float*)d_in[3];
    const float* W1   = (const float*)d_in[4];
    const float* W2   = (const float*)d_in[5];

    int n = in_sizes[0] / DDIM;                 // 8192
    if (n > NTOK) n = NTOK;

    float* out = (float*)d_out;

    // Optional concatenated tail outputs: out(N*D), expert_ids(2N), gate(2N), group_idx(N)
    size_t need = (size_t)n * DDIM + 5 * (size_t)n;
    float* o_eid  = nullptr;
    float* o_gate = nullptr;
    float* o_grp  = nullptr;
    if ((size_t)out_size >= need) {
        o_eid  = out + (size_t)n * DDIM;
        o_gate = o_eid + 2 * (size_t)n;
        o_grp  = o_gate + 2 * (size_t)n;
    }

    init_kernel<<<1, 128>>>();
    routing_kernel<<<(n + 7) / 8, 256>>>(h, Wg, bg, Wloc, o_eid, o_gate, o_grp, n);
    prefix_kernel<<<1, 64>>>();
    scatter_kernel<<<(2 * n + 255) / 256, 256>>>(n);
    // Both slots in one wave: slot0 tiles write `out`, slot1 tiles write g_extra
    expert_kernel<<<384, 256>>>(h, W1, W2, out);
    // out += g_extra
    add_kernel<<<1024, 256>>>(out, n * DDIM / 4);
}